// round 7
// baseline (speedup 1.0000x reference)
#include <cuda_runtime.h>
#include <cuda_bf16.h>
#include <math.h>
#include <stdint.h>

// ---------------------------------------------------------------------------
// BagAttentionNet forward.
//   h-chain (512->256->256->128, relu) on mma.sync bf16 (HMMA) with
//   3-split/6-product exact-fp32 emulation. D-chain + tail: SIMT fp32.
// ---------------------------------------------------------------------------

#define NB 2048
#define CI 64
#define MR (NB * CI)          // 131072
#define TAU_F 0.95f

typedef unsigned long long ull;

// ---------------- scratch (__device__ globals; no allocs allowed) ----------
__device__ __nv_bfloat16 g_xs [3ULL * MR * 512];   // x planes  [3][M][512]
__device__ __nv_bfloat16 g_h1p[3ULL * MR * 256];   // h1 planes [3][M][256]
__device__ __nv_bfloat16 g_h2p[3ULL * MR * 256];   // h2 planes [3][M][256]
__device__ __nv_bfloat16 g_w1t[3 * 512 * 256];     // W1^T planes [3][256][512]
__device__ __nv_bfloat16 g_w2t[3 * 256 * 256];     // W2^T planes [3][256][256]
__device__ __nv_bfloat16 g_w3t[3 * 256 * 128];     // W3^T planes [3][128][256]
__device__ float g_h3[MR * 128];
__device__ float g_d1[MR * 128];
__device__ float g_d2[MR * 64];
__device__ float g_dd[MR];

// ---------------- helpers ----------------------------------------------------
__device__ __forceinline__ void cp_async16(void* s, const void* g) {
    unsigned sa = (unsigned)__cvta_generic_to_shared(s);
    asm volatile("cp.async.cg.shared.global [%0], [%1], 16;" :: "r"(sa), "l"(g));
}
#define CP_COMMIT() asm volatile("cp.async.commit_group;")

__device__ __forceinline__ void split3(float v, __nv_bfloat16& h,
                                       __nv_bfloat16& m, __nv_bfloat16& l) {
    h = __float2bfloat16(v);  float q = v - __bfloat162float(h);
    m = __float2bfloat16(q);  float s = q - __bfloat162float(m);
    l = __float2bfloat16(s);
}

__device__ __forceinline__ void ldsm_x4(uint32_t& r0, uint32_t& r1,
                                        uint32_t& r2, uint32_t& r3, uint32_t addr) {
    asm volatile("ldmatrix.sync.aligned.m8n8.x4.shared.b16 {%0,%1,%2,%3},[%4];"
        : "=r"(r0), "=r"(r1), "=r"(r2), "=r"(r3) : "r"(addr));
}

__device__ __forceinline__ void hmma16816(float* c, const uint32_t* a, const uint32_t* b) {
    asm volatile("mma.sync.aligned.m16n8k16.row.col.f32.bf16.bf16.f32 "
        "{%0,%1,%2,%3},{%4,%5,%6,%7},{%8,%9},{%0,%1,%2,%3};"
        : "+f"(c[0]), "+f"(c[1]), "+f"(c[2]), "+f"(c[3])
        : "r"(a[0]), "r"(a[1]), "r"(a[2]), "r"(a[3]), "r"(b[0]), "r"(b[1]));
}

// ---------------- split kernels ----------------------------------------------
__global__ void split_x_kernel(const float* __restrict__ x,
                               __nv_bfloat16* __restrict__ o, size_t n) {
    size_t i = ((size_t)blockIdx.x * blockDim.x + threadIdx.x) * 4;
    if (i >= n) return;
    float4 v = *(const float4*)(x + i);
    float vv[4] = {v.x, v.y, v.z, v.w};
    __nv_bfloat16 h[4], m[4], l[4];
#pragma unroll
    for (int j = 0; j < 4; j++) split3(vv[j], h[j], m[j], l[j]);
    *(__nv_bfloat162*)(o + i)           = __halves2bfloat162(h[0], h[1]);
    *(__nv_bfloat162*)(o + i + 2)       = __halves2bfloat162(h[2], h[3]);
    *(__nv_bfloat162*)(o + n + i)       = __halves2bfloat162(m[0], m[1]);
    *(__nv_bfloat162*)(o + n + i + 2)   = __halves2bfloat162(m[2], m[3]);
    *(__nv_bfloat162*)(o + 2*n + i)     = __halves2bfloat162(l[0], l[1]);
    *(__nv_bfloat162*)(o + 2*n + i + 2) = __halves2bfloat162(l[2], l[3]);
}

// W[K][N] -> planes [3][N][K] (transpose + split)
__global__ void split_wt_kernel(const float* __restrict__ W,
                                __nv_bfloat16* __restrict__ o, int K, int N) {
    int idx = blockIdx.x * blockDim.x + threadIdx.x;
    if (idx >= K * N) return;
    int k = idx / N, n = idx % N;
    __nv_bfloat16 h, m, l;
    split3(W[idx], h, m, l);
    size_t pl = (size_t)K * N;
    size_t off = (size_t)n * K + k;
    o[off] = h; o[pl + off] = m; o[2 * pl + off] = l;
}

// ---------------- HMMA split GEMM --------------------------------------------
// A planes [3][M][K] bf16, B planes [3][ldN][K] bf16 (=W^T).
// C(128x128 per CTA) = sum over 6 products (hh,hm,mh,mm,hl,lh) of Apa @ Bpb^T.
// OUTMODE 0: relu -> 3 bf16 planes; OUTMODE 1: relu -> fp32.
#define TROW 80                            // 64B data + 16B pad (conflict-free)
#define TILE_B (128 * TROW)                // 10240
#define STAGE_B (6 * TILE_B)               // 61440
#define HSMEM (2 * STAGE_B)                // 122880

template<int OUTMODE>
__global__ void __launch_bounds__(256, 1)
hmma_gemm(const __nv_bfloat16* __restrict__ Ap, const __nv_bfloat16* __restrict__ Bp,
          const float* __restrict__ bias, void* __restrict__ Cout,
          int K, int ldN)
{
    extern __shared__ char smem[];
    __shared__ float sbias[128];
    const uint32_t sb = (uint32_t)__cvta_generic_to_shared(smem);
    const int tid = threadIdx.x, wid = tid >> 5, lane = tid & 31;
    const int brow = blockIdx.y * 128, bcol = blockIdx.x * 128;
    const int mbase = (wid >> 2) * 64;       // warp 64x32 tile
    const int nbase = (wid & 3) * 32;
    const size_t aplane = (size_t)MR * K;
    const size_t bplane = (size_t)ldN * K;

    if (tid < 128) sbias[tid] = bias[bcol + tid];

    const char* Ag = (const char*)(Ap);
    const char* Bg = (const char*)(Bp);
    const int crow = tid >> 2;              // 0..63? 256 thr: chunk row
    const int ccol = (tid & 3) * 16;

    auto load_kt = [&](int kt, int buf) {
        char* st = smem + buf * STAGE_B;
        const size_t kb = (size_t)kt * 64;
#pragma unroll
        for (int half = 0; half < 2; half++) {
            int row = crow + half * 64;
#pragma unroll
            for (int p = 0; p < 3; p++) {
                cp_async16(st + p * TILE_B + row * TROW + ccol,
                    Ag + ((size_t)p * aplane + (size_t)(brow + row) * K) * 2 + kb + ccol);
                cp_async16(st + (3 + p) * TILE_B + row * TROW + ccol,
                    Bg + ((size_t)p * bplane + (size_t)(bcol + row) * K) * 2 + kb + ccol);
            }
        }
    };

    float acc[4][4][4];
#pragma unroll
    for (int i = 0; i < 4; i++)
#pragma unroll
        for (int j = 0; j < 4; j++)
#pragma unroll
            for (int q = 0; q < 4; q++) acc[i][j][q] = 0.f;

    const int NT = K / 32;
    load_kt(0, 0); CP_COMMIT();

    // ldmatrix lane-address components (warp-invariant parts folded in)
    const int a_r  = (lane & 15);                 // row within m16
    const int a_kc = (lane & 16) ? 16 : 0;        // byte offset for k8 half (8*2B)
    const int b_n  = (lane & 7) + ((lane & 16) ? 8 : 0);
    const int b_kc = (lane & 8) ? 16 : 0;

    const int pa[6] = {0, 0, 1, 1, 0, 2};
    const int pb[6] = {0, 1, 0, 1, 2, 0};

    for (int kt = 0; kt < NT; kt++) {
        const int buf = kt & 1;
        if (kt + 1 < NT) { load_kt(kt + 1, buf ^ 1); CP_COMMIT(); }
        if (kt + 1 < NT) asm volatile("cp.async.wait_group 1;");
        else             asm volatile("cp.async.wait_group 0;");
        __syncthreads();

        const uint32_t stb = sb + buf * STAGE_B;
#pragma unroll
        for (int k16 = 0; k16 < 2; k16++) {
            const int kk = k16 * 32;    // byte offset of k16 within 64B row

            uint32_t afr[3][4][4];
#pragma unroll
            for (int p = 0; p < 3; p++) {
                uint32_t base = stb + p * TILE_B + kk + a_kc;
#pragma unroll
                for (int mf = 0; mf < 4; mf++) {
                    uint32_t ad = base + (mbase + mf * 16 + a_r) * TROW;
                    ldsm_x4(afr[p][mf][0], afr[p][mf][1], afr[p][mf][2], afr[p][mf][3], ad);
                }
            }
            uint32_t bfr[3][4][2];
#pragma unroll
            for (int p = 0; p < 3; p++) {
                uint32_t base = stb + (3 + p) * TILE_B + kk + b_kc;
#pragma unroll
                for (int nf2 = 0; nf2 < 2; nf2++) {
                    uint32_t bd = base + (nbase + nf2 * 16 + b_n) * TROW;
                    uint32_t r0, r1, r2, r3;
                    ldsm_x4(r0, r1, r2, r3, bd);
                    bfr[p][nf2 * 2 + 0][0] = r0; bfr[p][nf2 * 2 + 0][1] = r1;
                    bfr[p][nf2 * 2 + 1][0] = r2; bfr[p][nf2 * 2 + 1][1] = r3;
                }
            }
#pragma unroll
            for (int pr = 0; pr < 6; pr++) {
#pragma unroll
                for (int mf = 0; mf < 4; mf++)
#pragma unroll
                    for (int nf = 0; nf < 4; nf++)
                        hmma16816(acc[mf][nf], afr[pa[pr]][mf], bfr[pb[pr]][nf]);
            }
        }
        __syncthreads();
    }

    // ---- epilogue ----
    const int qr = lane >> 2, qc = (lane & 3) * 2;
#pragma unroll
    for (int mf = 0; mf < 4; mf++) {
#pragma unroll
        for (int half = 0; half < 2; half++) {
            const int row = brow + mbase + mf * 16 + qr + half * 8;
#pragma unroll
            for (int nf = 0; nf < 4; nf++) {
                const int colL = nbase + nf * 8 + qc;
                float v0 = fmaxf(acc[mf][nf][half * 2 + 0] + sbias[colL],     0.f);
                float v1 = fmaxf(acc[mf][nf][half * 2 + 1] + sbias[colL + 1], 0.f);
                if (OUTMODE == 0) {
                    __nv_bfloat16* C = (__nv_bfloat16*)Cout;
                    const size_t pstr = (size_t)MR * ldN;
                    const size_t base = (size_t)row * ldN + bcol + colL;
                    __nv_bfloat16 h0, m0, l0, h1, m1, l1;
                    split3(v0, h0, m0, l0);
                    split3(v1, h1, m1, l1);
                    *(__nv_bfloat162*)(C + base)            = __halves2bfloat162(h0, h1);
                    *(__nv_bfloat162*)(C + pstr + base)     = __halves2bfloat162(m0, m1);
                    *(__nv_bfloat162*)(C + 2 * pstr + base) = __halves2bfloat162(l0, l1);
                } else {
                    float* C = (float*)Cout;
                    *(float2*)(C + (size_t)row * ldN + bcol + colL) = make_float2(v0, v1);
                }
            }
        }
    }
}

// ---------------- SIMT FFMA2 GEMM (D-chain) ----------------------------------
__device__ __forceinline__ float act_apply(float v, int ACT) {
    if (ACT == 1) return v > 0.f ? v : 0.f;
    if (ACT == 2) return __fdividef(1.f, 1.f + __expf(-v));
    return v;
}

template<int BM, int BN, int BK, int ACT>
__global__ void __launch_bounds__((BM / 16) * (BN / 4), 2)
gemm2(const float* __restrict__ A, const float* __restrict__ W,
      const float* __restrict__ bias, float* __restrict__ Cmat,
      int K, int N)
{
    constexpr int TN = 4;
    constexpr int RX = BN / TN, RY = BM / 16, THREADS = RX * RY;
    constexpr int GROUPS = THREADS / BM;
    constexpr int KC  = BK / GROUPS;
    constexpr int AF4 = KC / 4;
    constexpr int WC  = (BK * BN) / (4 * THREADS);
    constexpr int BMP = BM + 4;
    constexpr int N4  = BN / 4;

    extern __shared__ float smemf[];
    float (*As)[BK][BMP] = (float (*)[BK][BMP])smemf;
    float (*Ws)[BK][BN]  = (float (*)[BK][BN])(smemf + 2 * BK * BMP);

    const int tid  = threadIdx.x;
    const int tcol = tid % RX;
    const int trow = tid / RX;
    const int brow = blockIdx.y * BM;
    const int bcol = blockIdx.x * BN;

    const int arow = tid % BM;
    const int akb  = (tid / BM) * KC;
    const float* Arow = A + (size_t)(brow + arow) * K + akb;

    ull acc2[8][TN];
#pragma unroll
    for (int i = 0; i < 8; i++)
#pragma unroll
        for (int j = 0; j < TN; j++) acc2[i][j] = 0ull;

    float4 areg[AF4];
    const int nt = K / BK;

#pragma unroll
    for (int q = 0; q < AF4; q++) areg[q] = *(const float4*)(Arow + q * 4);
#pragma unroll
    for (int i = 0; i < WC; i++) {
        int idx = tid + i * THREADS;
        int k = idx / N4, n4 = idx % N4;
        cp_async16(&Ws[0][k][n4 * 4], W + (size_t)k * N + bcol + n4 * 4);
    }
    CP_COMMIT();
#pragma unroll
    for (int q = 0; q < AF4; q++) {
        As[0][akb + q * 4 + 0][arow] = areg[q].x;
        As[0][akb + q * 4 + 1][arow] = areg[q].y;
        As[0][akb + q * 4 + 2][arow] = areg[q].z;
        As[0][akb + q * 4 + 3][arow] = areg[q].w;
    }
    asm volatile("cp.async.wait_group 0;");
    __syncthreads();

    for (int t = 0; t < nt; t++) {
        const int cb = t & 1;
        const bool more = (t + 1 < nt);
        if (more) {
            const float* Ap2 = Arow + (size_t)(t + 1) * BK;
#pragma unroll
            for (int q = 0; q < AF4; q++) areg[q] = *(const float4*)(Ap2 + q * 4);
            const float* Wp = W + (size_t)(t + 1) * BK * N + bcol;
#pragma unroll
            for (int i = 0; i < WC; i++) {
                int idx = tid + i * THREADS;
                int k = idx / N4, n4 = idx % N4;
                cp_async16(&Ws[cb ^ 1][k][n4 * 4], Wp + (size_t)k * N + n4 * 4);
            }
            CP_COMMIT();
        }
#pragma unroll
        for (int k = 0; k < BK; k++) {
            float4 wv = *(const float4*)&Ws[cb][k][tcol * 4];
            ull wb0, wb1, wb2, wb3;
            asm("mov.b64 %0, {%1, %1};" : "=l"(wb0) : "f"(wv.x));
            asm("mov.b64 %0, {%1, %1};" : "=l"(wb1) : "f"(wv.y));
            asm("mov.b64 %0, {%1, %1};" : "=l"(wb2) : "f"(wv.z));
            asm("mov.b64 %0, {%1, %1};" : "=l"(wb3) : "f"(wv.w));
            const float* ab = &As[cb][k][trow * 16];
            ulonglong2 p01 = *(const ulonglong2*)(ab + 0);
            ulonglong2 p23 = *(const ulonglong2*)(ab + 4);
            ulonglong2 p45 = *(const ulonglong2*)(ab + 8);
            ulonglong2 p67 = *(const ulonglong2*)(ab + 12);
            ull ap[8] = {p01.x, p01.y, p23.x, p23.y, p45.x, p45.y, p67.x, p67.y};
#pragma unroll
            for (int i = 0; i < 8; i++) {
                asm("fma.rn.f32x2 %0, %1, %2, %0;" : "+l"(acc2[i][0]) : "l"(ap[i]), "l"(wb0));
                asm("fma.rn.f32x2 %0, %1, %2, %0;" : "+l"(acc2[i][1]) : "l"(ap[i]), "l"(wb1));
                asm("fma.rn.f32x2 %0, %1, %2, %0;" : "+l"(acc2[i][2]) : "l"(ap[i]), "l"(wb2));
                asm("fma.rn.f32x2 %0, %1, %2, %0;" : "+l"(acc2[i][3]) : "l"(ap[i]), "l"(wb3));
            }
        }
        if (more) {
#pragma unroll
            for (int q = 0; q < AF4; q++) {
                As[cb ^ 1][akb + q * 4 + 0][arow] = areg[q].x;
                As[cb ^ 1][akb + q * 4 + 1][arow] = areg[q].y;
                As[cb ^ 1][akb + q * 4 + 2][arow] = areg[q].z;
                As[cb ^ 1][akb + q * 4 + 3][arow] = areg[q].w;
            }
            asm volatile("cp.async.wait_group 0;");
        }
        __syncthreads();
    }

    const int colb = bcol + tcol * 4;
    float4 bv = *(const float4*)(bias + colb);
#pragma unroll
    for (int i2 = 0; i2 < 8; i2++) {
        int row0 = brow + trow * 16 + 2 * i2;
        float e0, o0, e1, o1, e2, o2, e3, o3;
        asm("mov.b64 {%0, %1}, %2;" : "=f"(e0), "=f"(o0) : "l"(acc2[i2][0]));
        asm("mov.b64 {%0, %1}, %2;" : "=f"(e1), "=f"(o1) : "l"(acc2[i2][1]));
        asm("mov.b64 {%0, %1}, %2;" : "=f"(e2), "=f"(o2) : "l"(acc2[i2][2]));
        asm("mov.b64 {%0, %1}, %2;" : "=f"(e3), "=f"(o3) : "l"(acc2[i2][3]));
        float4 re, ro;
        re.x = act_apply(e0 + bv.x, ACT); re.y = act_apply(e1 + bv.y, ACT);
        re.z = act_apply(e2 + bv.z, ACT); re.w = act_apply(e3 + bv.w, ACT);
        ro.x = act_apply(o0 + bv.x, ACT); ro.y = act_apply(o1 + bv.y, ACT);
        ro.z = act_apply(o2 + bv.z, ACT); ro.w = act_apply(o3 + bv.w, ACT);
        *(float4*)(Cmat + (size_t)row0 * N + colb)       = re;
        *(float4*)(Cmat + (size_t)(row0 + 1) * N + colb) = ro;
    }
}

// d[r] = d2[r,:] . D3 + db3   (K = 64)
__global__ void dot_kernel(const float* __restrict__ d2, const float* __restrict__ D3,
                           const float* __restrict__ db3, float* __restrict__ dd)
{
    int gw   = (blockIdx.x * blockDim.x + threadIdx.x) >> 5;
    int lane = threadIdx.x & 31;
    if (gw >= MR) return;
    const float* row = d2 + (size_t)gw * 64;
    float s = row[lane] * D3[lane] + row[lane + 32] * D3[lane + 32];
#pragma unroll
    for (int o = 16; o > 0; o >>= 1) s += __shfl_down_sync(0xffffffffu, s, o);
    if (lane == 0) dd[gw] = s + db3[0];
}

// Per-bag: gumbel softmax, top-20 keep (stable), re-softmax, aggregate, project.
__global__ void __launch_bounds__(128)
final_kernel(const float* __restrict__ dd, const float* __restrict__ m,
             const float* __restrict__ u, const float* __restrict__ h3,
             const float* __restrict__ E, const float* __restrict__ eb,
             float* __restrict__ out_w, float* __restrict__ out_s)
{
    const int bag = blockIdx.x;
    const int t   = threadIdx.x;

    __shared__ float sm[64];
    __shared__ float wf[64];
    __shared__ float red[128];

    float z = 0.f;
    if (t < 64) {
        float logit = m[bag * 64 + t] * dd[bag * 64 + t];
        float uu = u[bag * 64 + t];
        float g = -logf(-logf(uu));
        z = (logit + g) / TAU_F;
    }

    red[t] = (t < 64) ? z : -INFINITY;
    __syncthreads();
#pragma unroll
    for (int s = 64; s >= 1; s >>= 1) {
        if (t < s) red[t] = fmaxf(red[t], red[t + s]);
        __syncthreads();
    }
    float zmax = red[0];
    __syncthreads();

    float e = (t < 64) ? expf(z - zmax) : 0.f;
    red[t] = e;
    __syncthreads();
#pragma unroll
    for (int s = 64; s >= 1; s >>= 1) {
        if (t < s) red[t] += red[t + s];
        __syncthreads();
    }
    float psum = red[0];
    __syncthreads();

    float p = e / psum;
    if (t < 64) sm[t] = p;
    __syncthreads();

    int keep = 0;
    if (t < 64) {
        int pos = 0;
#pragma unroll 8
        for (int j = 0; j < 64; j++) {
            float o = sm[j];
            pos += (o < p) || (o == p && j < t);
        }
        keep = (pos >= 44);
    }

    red[t] = (t < 64 && keep) ? p : -INFINITY;
    __syncthreads();
#pragma unroll
    for (int s = 64; s >= 1; s >>= 1) {
        if (t < s) red[t] = fmaxf(red[t], red[t + s]);
        __syncthreads();
    }
    float m2 = red[0];
    __syncthreads();

    float e2 = (t < 64 && keep) ? expf(p - m2) : 0.f;
    red[t] = e2;
    __syncthreads();
#pragma unroll
    for (int s = 64; s >= 1; s >>= 1) {
        if (t < s) red[t] += red[t + s];
        __syncthreads();
    }
    float s2 = red[0];
    __syncthreads();

    float wfin = (t < 64 && keep) ? (e2 / s2) : 0.f;
    if (t < 64) {
        wf[t] = wfin;
        out_w[bag * 64 + t] = wfin;
    }
    __syncthreads();

    const float* hb = h3 + (size_t)bag * 64 * 128;
    float agg = 0.f;
#pragma unroll 8
    for (int c = 0; c < 64; c++) agg += wf[c] * hb[c * 128 + t];
    red[t] = agg * E[t];
    __syncthreads();
#pragma unroll
    for (int s = 64; s >= 1; s >>= 1) {
        if (t < s) red[t] += red[t + s];
        __syncthreads();
    }
    if (t == 0) out_s[bag] = red[0] + eb[0];
}

// ---------------- launch ------------------------------------------------------
extern "C" void kernel_launch(void* const* d_in, const int* in_sizes, int n_in,
                              void* d_out, int out_size)
{
    const float* x   = (const float*)d_in[0];
    const float* m   = (const float*)d_in[1];
    const float* u   = (const float*)d_in[2];
    const float* W1  = (const float*)d_in[3];
    const float* b1  = (const float*)d_in[4];
    const float* W2  = (const float*)d_in[5];
    const float* b2  = (const float*)d_in[6];
    const float* W3  = (const float*)d_in[7];
    const float* b3  = (const float*)d_in[8];
    const float* D1  = (const float*)d_in[9];
    const float* db1 = (const float*)d_in[10];
    const float* D2  = (const float*)d_in[11];
    const float* db2 = (const float*)d_in[12];
    const float* D3  = (const float*)d_in[13];
    const float* db3 = (const float*)d_in[14];
    const float* E   = (const float*)d_in[15];
    const float* eb  = (const float*)d_in[16];
    float* out = (float*)d_out;

    __nv_bfloat16 *xs, *h1p, *h2p, *w1t, *w2t, *w3t;
    float *h3, *d1, *d2, *dd;
    cudaGetSymbolAddress((void**)&xs,  g_xs);
    cudaGetSymbolAddress((void**)&h1p, g_h1p);
    cudaGetSymbolAddress((void**)&h2p, g_h2p);
    cudaGetSymbolAddress((void**)&w1t, g_w1t);
    cudaGetSymbolAddress((void**)&w2t, g_w2t);
    cudaGetSymbolAddress((void**)&w3t, g_w3t);
    cudaGetSymbolAddress((void**)&h3,  g_h3);
    cudaGetSymbolAddress((void**)&d1,  g_d1);
    cudaGetSymbolAddress((void**)&d2,  g_d2);
    cudaGetSymbolAddress((void**)&dd,  g_dd);

    constexpr int S128 = (2 * 32 * 132 + 2 * 32 * 128) * 4;
    constexpr int S64  = (2 * 16 * 132 + 2 * 16 * 64) * 4;

    static int attr_done = 0;
    if (!attr_done) {
        cudaFuncSetAttribute(hmma_gemm<0>, cudaFuncAttributeMaxDynamicSharedMemorySize, HSMEM);
        cudaFuncSetAttribute(hmma_gemm<1>, cudaFuncAttributeMaxDynamicSharedMemorySize, HSMEM);
        cudaFuncSetAttribute(gemm2<128,128,32,2>, cudaFuncAttributeMaxDynamicSharedMemorySize, S128);
        cudaFuncSetAttribute(gemm2<128, 64,16,2>, cudaFuncAttributeMaxDynamicSharedMemorySize, S64);
        attr_done = 1;
    }

    // splits
    split_x_kernel<<<(MR * 512 / 4 + 255) / 256, 256>>>(x, xs, (size_t)MR * 512);
    split_wt_kernel<<<(512 * 256 + 255) / 256, 256>>>(W1, w1t, 512, 256);
    split_wt_kernel<<<(256 * 256 + 255) / 256, 256>>>(W2, w2t, 256, 256);
    split_wt_kernel<<<(256 * 128 + 255) / 256, 256>>>(W3, w3t, 256, 128);

    // h-chain on HMMA (exact-fp32 via 3-split/6-product)
    hmma_gemm<0><<<dim3(2, MR / 128), 256, HSMEM>>>(xs,  w1t, b1, h1p, 512, 256);
    hmma_gemm<0><<<dim3(2, MR / 128), 256, HSMEM>>>(h1p, w2t, b2, h2p, 256, 256);
    hmma_gemm<1><<<dim3(1, MR / 128), 256, HSMEM>>>(h2p, w3t, b3, h3,  256, 128);

    // D-chain (SIMT FFMA2)
    gemm2<128,128,32,2><<<dim3(1, MR / 128), 256, S128>>>(h3, D1, db1, d1, 128, 128);
    gemm2<128, 64,16,2><<<dim3(1, MR / 128), 128, S64>>>(d1, D2, db2, d2, 128, 64);
    dot_kernel<<<MR / 8, 256>>>(d2, D3, db3, dd);
    final_kernel<<<NB, 128>>>(dd, m, u, h3, E, eb, out, out + MR);
}

// round 8
// speedup vs baseline: 1.0270x; 1.0270x over previous
#include <cuda_runtime.h>
#include <cuda_bf16.h>
#include <math.h>
#include <stdint.h>

// ---------------------------------------------------------------------------
// BagAttentionNet forward.
//   h-chain (512->256->256->128, relu) on mma.sync bf16 (HMMA) with
//   3-split/6-product exact-fp32 emulation. Layer 1 fuses the fp32->3xbf16
//   split of x in-kernel (FUSEA). D-chain + tail: SIMT fp32 (FFMA2).
// ---------------------------------------------------------------------------

#define NB 2048
#define CI 64
#define MR (NB * CI)          // 131072
#define TAU_F 0.95f

typedef unsigned long long ull;

// ---------------- scratch (__device__ globals; no allocs allowed) ----------
__device__ __nv_bfloat16 g_h1p[3ULL * MR * 256];   // h1 planes [3][M][256]
__device__ __nv_bfloat16 g_h2p[3ULL * MR * 256];   // h2 planes [3][M][256]
__device__ __nv_bfloat16 g_w1t[3 * 512 * 256];     // W1^T planes [3][256][512]
__device__ __nv_bfloat16 g_w2t[3 * 256 * 256];     // W2^T planes [3][256][256]
__device__ __nv_bfloat16 g_w3t[3 * 256 * 128];     // W3^T planes [3][128][256]
__device__ float g_h3[MR * 128];
__device__ float g_d1[MR * 128];
__device__ float g_d2[MR * 64];
__device__ float g_dd[MR];

// ---------------- helpers ----------------------------------------------------
__device__ __forceinline__ void cp_async16(void* s, const void* g) {
    unsigned sa = (unsigned)__cvta_generic_to_shared(s);
    asm volatile("cp.async.cg.shared.global [%0], [%1], 16;" :: "r"(sa), "l"(g));
}
#define CP_COMMIT() asm volatile("cp.async.commit_group;")

__device__ __forceinline__ void split3(float v, __nv_bfloat16& h,
                                       __nv_bfloat16& m, __nv_bfloat16& l) {
    h = __float2bfloat16(v);  float q = v - __bfloat162float(h);
    m = __float2bfloat16(q);  float s = q - __bfloat162float(m);
    l = __float2bfloat16(s);
}

__device__ __forceinline__ void ldsm_x4(uint32_t& r0, uint32_t& r1,
                                        uint32_t& r2, uint32_t& r3, uint32_t addr) {
    asm volatile("ldmatrix.sync.aligned.m8n8.x4.shared.b16 {%0,%1,%2,%3},[%4];"
        : "=r"(r0), "=r"(r1), "=r"(r2), "=r"(r3) : "r"(addr));
}

__device__ __forceinline__ void hmma16816(float* c, const uint32_t* a, const uint32_t* b) {
    asm volatile("mma.sync.aligned.m16n8k16.row.col.f32.bf16.bf16.f32 "
        "{%0,%1,%2,%3},{%4,%5,%6,%7},{%8,%9},{%0,%1,%2,%3};"
        : "+f"(c[0]), "+f"(c[1]), "+f"(c[2]), "+f"(c[3])
        : "r"(a[0]), "r"(a[1]), "r"(a[2]), "r"(a[3]), "r"(b[0]), "r"(b[1]));
}

// W[K][N] -> planes [3][N][K] (transpose + split)
__global__ void split_wt_kernel(const float* __restrict__ W,
                                __nv_bfloat16* __restrict__ o, int K, int N) {
    int idx = blockIdx.x * blockDim.x + threadIdx.x;
    if (idx >= K * N) return;
    int k = idx / N, n = idx % N;
    __nv_bfloat16 h, m, l;
    split3(W[idx], h, m, l);
    size_t pl = (size_t)K * N;
    size_t off = (size_t)n * K + k;
    o[off] = h; o[pl + off] = m; o[2 * pl + off] = l;
}

// ---------------- HMMA split GEMM --------------------------------------------
// FUSEA=0: A planes [3][M][K] bf16.  FUSEA=1: A is fp32 [M][K], split in-kernel.
// B planes [3][ldN][K] bf16 (=W^T).
// C(128x128 per CTA) = sum over 6 products (hh,hm,mh,mm,hl,lh).
// OUTMODE 0: relu -> 3 bf16 planes; OUTMODE 1: relu -> fp32.
#define TROW 80                            // 64B data + 16B pad
#define TILE_B (128 * TROW)                // 10240
#define STAGE_B (6 * TILE_B)               // 61440
#define FSTG_B  (128 * 144)                // fp32 A tile, 36-float row stride
#define FSTAGE_OFF (2 * STAGE_B)           // 122880
#define HSMEM   (2 * STAGE_B)              // 122880 (FUSEA=0)
#define HSMEM_F (2 * STAGE_B + 2 * FSTG_B) // 159744 (FUSEA=1)

template<int OUTMODE, int FUSEA>
__global__ void __launch_bounds__(256, 1)
hmma_gemm(const void* __restrict__ Apv, const __nv_bfloat16* __restrict__ Bp,
          const float* __restrict__ bias, void* __restrict__ Cout,
          int K, int ldN)
{
    extern __shared__ char smem[];
    __shared__ float sbias[128];
    const uint32_t sb = (uint32_t)__cvta_generic_to_shared(smem);
    const int tid = threadIdx.x, wid = tid >> 5, lane = tid & 31;
    const int brow = blockIdx.y * 128, bcol = blockIdx.x * 128;
    const int mbase = (wid >> 2) * 64;       // warp 64x32 tile
    const int nbase = (wid & 3) * 32;
    const size_t aplane = (size_t)MR * K;
    const size_t bplane = (size_t)ldN * K;

    if (tid < 128) sbias[tid] = bias[bcol + tid];

    const char* Ag = (const char*)Apv;
    const char* Bg = (const char*)Bp;
    const float* Af = (const float*)Apv;
    const int crow = tid >> 2;              // 0..63 (B / bf16-A chunk row)
    const int ccol = (tid & 3) * 16;

    auto load_kt = [&](int kt, int buf) {
        char* st = smem + buf * STAGE_B;
        const size_t kb = (size_t)kt * 64;   // bf16 bytes for 32 k
        // B planes (always bf16)
#pragma unroll
        for (int half = 0; half < 2; half++) {
            int row = crow + half * 64;
#pragma unroll
            for (int p = 0; p < 3; p++) {
                cp_async16(st + (3 + p) * TILE_B + row * TROW + ccol,
                    Bg + ((size_t)p * bplane + (size_t)(bcol + row) * K) * 2 + kb + ccol);
            }
        }
        if (FUSEA) {
            // fp32 x tile -> staged; 1024 16B chunks, 4 per thread
            char* fs = smem + FSTAGE_OFF + buf * FSTG_B;
#pragma unroll
            for (int i = 0; i < 4; i++) {
                int c = tid + i * 256;
                int row = c >> 3, col = c & 7;
                cp_async16(fs + row * 144 + col * 16,
                    (const char*)(Af + (size_t)(brow + row) * K + kt * 32 + col * 4));
            }
        } else {
#pragma unroll
            for (int half = 0; half < 2; half++) {
                int row = crow + half * 64;
#pragma unroll
                for (int p = 0; p < 3; p++) {
                    cp_async16(st + p * TILE_B + row * TROW + ccol,
                        Ag + ((size_t)p * aplane + (size_t)(brow + row) * K) * 2 + kb + ccol);
                }
            }
        }
    };

    // fp32 stage -> 3 bf16 A-plane tiles (FUSEA only)
    auto convert_a = [&](int buf) {
        const int r = tid >> 1, half = tid & 1;
        const float* src = (const float*)(smem + FSTAGE_OFF + buf * FSTG_B) + r * 36 + half * 16;
        char* ap = smem + buf * STAGE_B;
        const uint32_t ro = r * TROW + half * 32;
#pragma unroll
        for (int j = 0; j < 4; j++) {
            float4 v = *(const float4*)(src + j * 4);
            float vv[4] = {v.x, v.y, v.z, v.w};
            __nv_bfloat16 h[4], mm[4], l[4];
#pragma unroll
            for (int e = 0; e < 4; e++) split3(vv[e], h[e], mm[e], l[e]);
            *(__nv_bfloat162*)(ap + ro + j * 8)                  = __halves2bfloat162(h[0], h[1]);
            *(__nv_bfloat162*)(ap + ro + j * 8 + 4)              = __halves2bfloat162(h[2], h[3]);
            *(__nv_bfloat162*)(ap + TILE_B + ro + j * 8)         = __halves2bfloat162(mm[0], mm[1]);
            *(__nv_bfloat162*)(ap + TILE_B + ro + j * 8 + 4)     = __halves2bfloat162(mm[2], mm[3]);
            *(__nv_bfloat162*)(ap + 2 * TILE_B + ro + j * 8)     = __halves2bfloat162(l[0], l[1]);
            *(__nv_bfloat162*)(ap + 2 * TILE_B + ro + j * 8 + 4) = __halves2bfloat162(l[2], l[3]);
        }
    };

    float acc[4][4][4];
#pragma unroll
    for (int i = 0; i < 4; i++)
#pragma unroll
        for (int j = 0; j < 4; j++)
#pragma unroll
            for (int q = 0; q < 4; q++) acc[i][j][q] = 0.f;

    const int NT = K / 32;
    load_kt(0, 0); CP_COMMIT();

    const int a_r  = (lane & 15);
    const int a_kc = (lane & 16) ? 16 : 0;
    const int b_n  = (lane & 7) + ((lane & 16) ? 8 : 0);
    const int b_kc = (lane & 8) ? 16 : 0;

    const int pa[6] = {0, 0, 1, 1, 0, 2};
    const int pb[6] = {0, 1, 0, 1, 2, 0};

    for (int kt = 0; kt < NT; kt++) {
        const int buf = kt & 1;
        if (kt + 1 < NT) { load_kt(kt + 1, buf ^ 1); CP_COMMIT(); }
        if (kt + 1 < NT) asm volatile("cp.async.wait_group 1;");
        else             asm volatile("cp.async.wait_group 0;");
        __syncthreads();
        if (FUSEA) { convert_a(buf); __syncthreads(); }

        const uint32_t stb = sb + buf * STAGE_B;
#pragma unroll
        for (int k16 = 0; k16 < 2; k16++) {
            const int kk = k16 * 32;

            uint32_t afr[3][4][4];
#pragma unroll
            for (int p = 0; p < 3; p++) {
                uint32_t base = stb + p * TILE_B + kk + a_kc;
#pragma unroll
                for (int mf = 0; mf < 4; mf++) {
                    uint32_t ad = base + (mbase + mf * 16 + a_r) * TROW;
                    ldsm_x4(afr[p][mf][0], afr[p][mf][1], afr[p][mf][2], afr[p][mf][3], ad);
                }
            }
            uint32_t bfr[3][4][2];
#pragma unroll
            for (int p = 0; p < 3; p++) {
                uint32_t base = stb + (3 + p) * TILE_B + kk + b_kc;
#pragma unroll
                for (int nf2 = 0; nf2 < 2; nf2++) {
                    uint32_t bd = base + (nbase + nf2 * 16 + b_n) * TROW;
                    uint32_t r0, r1, r2, r3;
                    ldsm_x4(r0, r1, r2, r3, bd);
                    bfr[p][nf2 * 2 + 0][0] = r0; bfr[p][nf2 * 2 + 0][1] = r1;
                    bfr[p][nf2 * 2 + 1][0] = r2; bfr[p][nf2 * 2 + 1][1] = r3;
                }
            }
#pragma unroll
            for (int pr = 0; pr < 6; pr++) {
#pragma unroll
                for (int mf = 0; mf < 4; mf++)
#pragma unroll
                    for (int nf = 0; nf < 4; nf++)
                        hmma16816(acc[mf][nf], afr[pa[pr]][mf], bfr[pb[pr]][nf]);
            }
        }
        __syncthreads();
    }

    // ---- epilogue ----
    const int qr = lane >> 2, qc = (lane & 3) * 2;
#pragma unroll
    for (int mf = 0; mf < 4; mf++) {
#pragma unroll
        for (int half = 0; half < 2; half++) {
            const int row = brow + mbase + mf * 16 + qr + half * 8;
#pragma unroll
            for (int nf = 0; nf < 4; nf++) {
                const int colL = nbase + nf * 8 + qc;
                float v0 = fmaxf(acc[mf][nf][half * 2 + 0] + sbias[colL],     0.f);
                float v1 = fmaxf(acc[mf][nf][half * 2 + 1] + sbias[colL + 1], 0.f);
                if (OUTMODE == 0) {
                    __nv_bfloat16* C = (__nv_bfloat16*)Cout;
                    const size_t pstr = (size_t)MR * ldN;
                    const size_t base = (size_t)row * ldN + bcol + colL;
                    __nv_bfloat16 h0, m0, l0, h1, m1, l1;
                    split3(v0, h0, m0, l0);
                    split3(v1, h1, m1, l1);
                    *(__nv_bfloat162*)(C + base)            = __halves2bfloat162(h0, h1);
                    *(__nv_bfloat162*)(C + pstr + base)     = __halves2bfloat162(m0, m1);
                    *(__nv_bfloat162*)(C + 2 * pstr + base) = __halves2bfloat162(l0, l1);
                } else {
                    float* C = (float*)Cout;
                    *(float2*)(C + (size_t)row * ldN + bcol + colL) = make_float2(v0, v1);
                }
            }
        }
    }
}

// ---------------- SIMT FFMA2 GEMM (D-chain) ----------------------------------
__device__ __forceinline__ float act_apply(float v, int ACT) {
    if (ACT == 1) return v > 0.f ? v : 0.f;
    if (ACT == 2) return __fdividef(1.f, 1.f + __expf(-v));
    return v;
}

template<int BM, int BN, int BK, int ACT>
__global__ void __launch_bounds__((BM / 16) * (BN / 4), 2)
gemm2(const float* __restrict__ A, const float* __restrict__ W,
      const float* __restrict__ bias, float* __restrict__ Cmat,
      int K, int N)
{
    constexpr int TN = 4;
    constexpr int RX = BN / TN, RY = BM / 16, THREADS = RX * RY;
    constexpr int GROUPS = THREADS / BM;
    constexpr int KC  = BK / GROUPS;
    constexpr int AF4 = KC / 4;
    constexpr int WC  = (BK * BN) / (4 * THREADS);
    constexpr int BMP = BM + 4;
    constexpr int N4  = BN / 4;

    extern __shared__ float smemf[];
    float (*As)[BK][BMP] = (float (*)[BK][BMP])smemf;
    float (*Ws)[BK][BN]  = (float (*)[BK][BN])(smemf + 2 * BK * BMP);

    const int tid  = threadIdx.x;
    const int tcol = tid % RX;
    const int trow = tid / RX;
    const int brow = blockIdx.y * BM;
    const int bcol = blockIdx.x * BN;

    const int arow = tid % BM;
    const int akb  = (tid / BM) * KC;
    const float* Arow = A + (size_t)(brow + arow) * K + akb;

    ull acc2[8][TN];
#pragma unroll
    for (int i = 0; i < 8; i++)
#pragma unroll
        for (int j = 0; j < TN; j++) acc2[i][j] = 0ull;

    float4 areg[AF4];
    const int nt = K / BK;

#pragma unroll
    for (int q = 0; q < AF4; q++) areg[q] = *(const float4*)(Arow + q * 4);
#pragma unroll
    for (int i = 0; i < WC; i++) {
        int idx = tid + i * THREADS;
        int k = idx / N4, n4 = idx % N4;
        cp_async16(&Ws[0][k][n4 * 4], W + (size_t)k * N + bcol + n4 * 4);
    }
    CP_COMMIT();
#pragma unroll
    for (int q = 0; q < AF4; q++) {
        As[0][akb + q * 4 + 0][arow] = areg[q].x;
        As[0][akb + q * 4 + 1][arow] = areg[q].y;
        As[0][akb + q * 4 + 2][arow] = areg[q].z;
        As[0][akb + q * 4 + 3][arow] = areg[q].w;
    }
    asm volatile("cp.async.wait_group 0;");
    __syncthreads();

    for (int t = 0; t < nt; t++) {
        const int cb = t & 1;
        const bool more = (t + 1 < nt);
        if (more) {
            const float* Ap2 = Arow + (size_t)(t + 1) * BK;
#pragma unroll
            for (int q = 0; q < AF4; q++) areg[q] = *(const float4*)(Ap2 + q * 4);
            const float* Wp = W + (size_t)(t + 1) * BK * N + bcol;
#pragma unroll
            for (int i = 0; i < WC; i++) {
                int idx = tid + i * THREADS;
                int k = idx / N4, n4 = idx % N4;
                cp_async16(&Ws[cb ^ 1][k][n4 * 4], Wp + (size_t)k * N + n4 * 4);
            }
            CP_COMMIT();
        }
#pragma unroll
        for (int k = 0; k < BK; k++) {
            float4 wv = *(const float4*)&Ws[cb][k][tcol * 4];
            ull wb0, wb1, wb2, wb3;
            asm("mov.b64 %0, {%1, %1};" : "=l"(wb0) : "f"(wv.x));
            asm("mov.b64 %0, {%1, %1};" : "=l"(wb1) : "f"(wv.y));
            asm("mov.b64 %0, {%1, %1};" : "=l"(wb2) : "f"(wv.z));
            asm("mov.b64 %0, {%1, %1};" : "=l"(wb3) : "f"(wv.w));
            const float* ab = &As[cb][k][trow * 16];
            ulonglong2 p01 = *(const ulonglong2*)(ab + 0);
            ulonglong2 p23 = *(const ulonglong2*)(ab + 4);
            ulonglong2 p45 = *(const ulonglong2*)(ab + 8);
            ulonglong2 p67 = *(const ulonglong2*)(ab + 12);
            ull ap[8] = {p01.x, p01.y, p23.x, p23.y, p45.x, p45.y, p67.x, p67.y};
#pragma unroll
            for (int i = 0; i < 8; i++) {
                asm("fma.rn.f32x2 %0, %1, %2, %0;" : "+l"(acc2[i][0]) : "l"(ap[i]), "l"(wb0));
                asm("fma.rn.f32x2 %0, %1, %2, %0;" : "+l"(acc2[i][1]) : "l"(ap[i]), "l"(wb1));
                asm("fma.rn.f32x2 %0, %1, %2, %0;" : "+l"(acc2[i][2]) : "l"(ap[i]), "l"(wb2));
                asm("fma.rn.f32x2 %0, %1, %2, %0;" : "+l"(acc2[i][3]) : "l"(ap[i]), "l"(wb3));
            }
        }
        if (more) {
#pragma unroll
            for (int q = 0; q < AF4; q++) {
                As[cb ^ 1][akb + q * 4 + 0][arow] = areg[q].x;
                As[cb ^ 1][akb + q * 4 + 1][arow] = areg[q].y;
                As[cb ^ 1][akb + q * 4 + 2][arow] = areg[q].z;
                As[cb ^ 1][akb + q * 4 + 3][arow] = areg[q].w;
            }
            asm volatile("cp.async.wait_group 0;");
        }
        __syncthreads();
    }

    const int colb = bcol + tcol * 4;
    float4 bv = *(const float4*)(bias + colb);
#pragma unroll
    for (int i2 = 0; i2 < 8; i2++) {
        int row0 = brow + trow * 16 + 2 * i2;
        float e0, o0, e1, o1, e2, o2, e3, o3;
        asm("mov.b64 {%0, %1}, %2;" : "=f"(e0), "=f"(o0) : "l"(acc2[i2][0]));
        asm("mov.b64 {%0, %1}, %2;" : "=f"(e1), "=f"(o1) : "l"(acc2[i2][1]));
        asm("mov.b64 {%0, %1}, %2;" : "=f"(e2), "=f"(o2) : "l"(acc2[i2][2]));
        asm("mov.b64 {%0, %1}, %2;" : "=f"(e3), "=f"(o3) : "l"(acc2[i2][3]));
        float4 re, ro;
        re.x = act_apply(e0 + bv.x, ACT); re.y = act_apply(e1 + bv.y, ACT);
        re.z = act_apply(e2 + bv.z, ACT); re.w = act_apply(e3 + bv.w, ACT);
        ro.x = act_apply(o0 + bv.x, ACT); ro.y = act_apply(o1 + bv.y, ACT);
        ro.z = act_apply(o2 + bv.z, ACT); ro.w = act_apply(o3 + bv.w, ACT);
        *(float4*)(Cmat + (size_t)row0 * N + colb)       = re;
        *(float4*)(Cmat + (size_t)(row0 + 1) * N + colb) = ro;
    }
}

// d[r] = d2[r,:] . D3 + db3   (K = 64)
__global__ void dot_kernel(const float* __restrict__ d2, const float* __restrict__ D3,
                           const float* __restrict__ db3, float* __restrict__ dd)
{
    int gw   = (blockIdx.x * blockDim.x + threadIdx.x) >> 5;
    int lane = threadIdx.x & 31;
    if (gw >= MR) return;
    const float* row = d2 + (size_t)gw * 64;
    float s = row[lane] * D3[lane] + row[lane + 32] * D3[lane + 32];
#pragma unroll
    for (int o = 16; o > 0; o >>= 1) s += __shfl_down_sync(0xffffffffu, s, o);
    if (lane == 0) dd[gw] = s + db3[0];
}

// Per-bag: gumbel softmax, top-20 keep (stable), re-softmax, aggregate, project.
__global__ void __launch_bounds__(128)
final_kernel(const float* __restrict__ dd, const float* __restrict__ m,
             const float* __restrict__ u, const float* __restrict__ h3,
             const float* __restrict__ E, const float* __restrict__ eb,
             float* __restrict__ out_w, float* __restrict__ out_s)
{
    const int bag = blockIdx.x;
    const int t   = threadIdx.x;

    __shared__ float sm[64];
    __shared__ float wf[64];
    __shared__ float red[128];

    float z = 0.f;
    if (t < 64) {
        float logit = m[bag * 64 + t] * dd[bag * 64 + t];
        float uu = u[bag * 64 + t];
        float g = -logf(-logf(uu));
        z = (logit + g) / TAU_F;
    }

    red[t] = (t < 64) ? z : -INFINITY;
    __syncthreads();
#pragma unroll
    for (int s = 64; s >= 1; s >>= 1) {
        if (t < s) red[t] = fmaxf(red[t], red[t + s]);
        __syncthreads();
    }
    float zmax = red[0];
    __syncthreads();

    float e = (t < 64) ? expf(z - zmax) : 0.f;
    red[t] = e;
    __syncthreads();
#pragma unroll
    for (int s = 64; s >= 1; s >>= 1) {
        if (t < s) red[t] += red[t + s];
        __syncthreads();
    }
    float psum = red[0];
    __syncthreads();

    float p = e / psum;
    if (t < 64) sm[t] = p;
    __syncthreads();

    int keep = 0;
    if (t < 64) {
        int pos = 0;
#pragma unroll 8
        for (int j = 0; j < 64; j++) {
            float o = sm[j];
            pos += (o < p) || (o == p && j < t);
        }
        keep = (pos >= 44);
    }

    red[t] = (t < 64 && keep) ? p : -INFINITY;
    __syncthreads();
#pragma unroll
    for (int s = 64; s >= 1; s >>= 1) {
        if (t < s) red[t] = fmaxf(red[t], red[t + s]);
        __syncthreads();
    }
    float m2 = red[0];
    __syncthreads();

    float e2 = (t < 64 && keep) ? expf(p - m2) : 0.f;
    red[t] = e2;
    __syncthreads();
#pragma unroll
    for (int s = 64; s >= 1; s >>= 1) {
        if (t < s) red[t] += red[t + s];
        __syncthreads();
    }
    float s2 = red[0];
    __syncthreads();

    float wfin = (t < 64 && keep) ? (e2 / s2) : 0.f;
    if (t < 64) {
        wf[t] = wfin;
        out_w[bag * 64 + t] = wfin;
    }
    __syncthreads();

    const float* hb = h3 + (size_t)bag * 64 * 128;
    float agg = 0.f;
#pragma unroll 8
    for (int c = 0; c < 64; c++) agg += wf[c] * hb[c * 128 + t];
    red[t] = agg * E[t];
    __syncthreads();
#pragma unroll
    for (int s = 64; s >= 1; s >>= 1) {
        if (t < s) red[t] += red[t + s];
        __syncthreads();
    }
    if (t == 0) out_s[bag] = red[0] + eb[0];
}

// ---------------- launch ------------------------------------------------------
extern "C" void kernel_launch(void* const* d_in, const int* in_sizes, int n_in,
                              void* d_out, int out_size)
{
    const float* x   = (const float*)d_in[0];
    const float* m   = (const float*)d_in[1];
    const float* u   = (const float*)d_in[2];
    const float* W1  = (const float*)d_in[3];
    const float* b1  = (const float*)d_in[4];
    const float* W2  = (const float*)d_in[5];
    const float* b2  = (const float*)d_in[6];
    const float* W3  = (const float*)d_in[7];
    const float* b3  = (const float*)d_in[8];
    const float* D1  = (const float*)d_in[9];
    const float* db1 = (const float*)d_in[10];
    const float* D2  = (const float*)d_in[11];
    const float* db2 = (const float*)d_in[12];
    const float* D3  = (const float*)d_in[13];
    const float* db3 = (const float*)d_in[14];
    const float* E   = (const float*)d_in[15];
    const float* eb  = (const float*)d_in[16];
    float* out = (float*)d_out;

    __nv_bfloat16 *h1p, *h2p, *w1t, *w2t, *w3t;
    float *h3, *d1, *d2, *dd;
    cudaGetSymbolAddress((void**)&h1p, g_h1p);
    cudaGetSymbolAddress((void**)&h2p, g_h2p);
    cudaGetSymbolAddress((void**)&w1t, g_w1t);
    cudaGetSymbolAddress((void**)&w2t, g_w2t);
    cudaGetSymbolAddress((void**)&w3t, g_w3t);
    cudaGetSymbolAddress((void**)&h3,  g_h3);
    cudaGetSymbolAddress((void**)&d1,  g_d1);
    cudaGetSymbolAddress((void**)&d2,  g_d2);
    cudaGetSymbolAddress((void**)&dd,  g_dd);

    constexpr int S128 = (2 * 32 * 132 + 2 * 32 * 128) * 4;
    constexpr int S64  = (2 * 16 * 132 + 2 * 16 * 64) * 4;

    static int attr_done = 0;
    if (!attr_done) {
        cudaFuncSetAttribute(hmma_gemm<0,1>, cudaFuncAttributeMaxDynamicSharedMemorySize, HSMEM_F);
        cudaFuncSetAttribute(hmma_gemm<0,0>, cudaFuncAttributeMaxDynamicSharedMemorySize, HSMEM);
        cudaFuncSetAttribute(hmma_gemm<1,0>, cudaFuncAttributeMaxDynamicSharedMemorySize, HSMEM);
        cudaFuncSetAttribute(gemm2<128,128,32,2>, cudaFuncAttributeMaxDynamicSharedMemorySize, S128);
        cudaFuncSetAttribute(gemm2<128, 64,16,2>, cudaFuncAttributeMaxDynamicSharedMemorySize, S64);
        attr_done = 1;
    }

    // weight splits (tiny)
    split_wt_kernel<<<(512 * 256 + 255) / 256, 256>>>(W1, w1t, 512, 256);
    split_wt_kernel<<<(256 * 256 + 255) / 256, 256>>>(W2, w2t, 256, 256);
    split_wt_kernel<<<(256 * 128 + 255) / 256, 256>>>(W3, w3t, 256, 128);

    // h-chain on HMMA (exact-fp32 via 3-split/6-product); layer 1 fuses x split
    hmma_gemm<0,1><<<dim3(2, MR / 128), 256, HSMEM_F>>>(x,   w1t, b1, h1p, 512, 256);
    hmma_gemm<0,0><<<dim3(2, MR / 128), 256, HSMEM>>>(h1p, w2t, b2, h2p, 256, 256);
    hmma_gemm<1,0><<<dim3(1, MR / 128), 256, HSMEM>>>(h2p, w3t, b3, h3,  256, 128);

    // D-chain (SIMT FFMA2)
    gemm2<128,128,32,2><<<dim3(1, MR / 128), 256, S128>>>(h3, D1, db1, d1, 128, 128);
    gemm2<128, 64,16,2><<<dim3(1, MR / 128), 128, S64>>>(d1, D2, db2, d2, 128, 64);
    dot_kernel<<<MR / 8, 256>>>(d2, D3, db3, dd);
    final_kernel<<<NB, 128>>>(dd, m, u, h3, E, eb, out, out + MR);
}

// round 10
// speedup vs baseline: 1.0535x; 1.0258x over previous
#include <cuda_runtime.h>
#include <cuda_bf16.h>
#include <math.h>
#include <stdint.h>

// ---------------------------------------------------------------------------
// BagAttentionNet forward.
//   h-chain (512->256->256->128, relu) on mma.sync bf16 (HMMA) with
//   3-split/6-product exact-fp32 emulation. All layers: fp32 in, in-kernel
//   split (overlapped with tensor drain), fp32 out. D-chain + tail: SIMT fp32.
// ---------------------------------------------------------------------------

#define NB 2048
#define CI 64
#define MR (NB * CI)          // 131072
#define TAU_F 0.95f

typedef unsigned long long ull;

// ---------------- scratch (__device__ globals; no allocs allowed) ----------
__device__ float g_h1f[(size_t)MR * 256];
__device__ float g_h2f[(size_t)MR * 256];
__device__ float g_h3 [(size_t)MR * 128];
__device__ float g_d1 [(size_t)MR * 128];
__device__ float g_d2 [(size_t)MR * 64];
__device__ float g_dd [MR];
__device__ __nv_bfloat16 g_w1t[3 * 512 * 256];     // W1^T planes [3][256][512]
__device__ __nv_bfloat16 g_w2t[3 * 256 * 256];     // W2^T planes [3][256][256]
__device__ __nv_bfloat16 g_w3t[3 * 256 * 128];     // W3^T planes [3][128][256]

// ---------------- helpers ----------------------------------------------------
__device__ __forceinline__ void cp_async16(void* s, const void* g) {
    unsigned sa = (unsigned)__cvta_generic_to_shared(s);
    asm volatile("cp.async.cg.shared.global [%0], [%1], 16;" :: "r"(sa), "l"(g));
}
#define CP_COMMIT() asm volatile("cp.async.commit_group;")

__device__ __forceinline__ void split3(float v, __nv_bfloat16& h,
                                       __nv_bfloat16& m, __nv_bfloat16& l) {
    h = __float2bfloat16(v);  float q = v - __bfloat162float(h);
    m = __float2bfloat16(q);  float s = q - __bfloat162float(m);
    l = __float2bfloat16(s);
}

__device__ __forceinline__ void ldsm_x4(uint32_t& r0, uint32_t& r1,
                                        uint32_t& r2, uint32_t& r3, uint32_t addr) {
    asm volatile("ldmatrix.sync.aligned.m8n8.x4.shared.b16 {%0,%1,%2,%3},[%4];"
        : "=r"(r0), "=r"(r1), "=r"(r2), "=r"(r3) : "r"(addr));
}

__device__ __forceinline__ void hmma16816(float* c, const uint32_t* a, const uint32_t* b) {
    asm volatile("mma.sync.aligned.m16n8k16.row.col.f32.bf16.bf16.f32 "
        "{%0,%1,%2,%3},{%4,%5,%6,%7},{%8,%9},{%0,%1,%2,%3};"
        : "+f"(c[0]), "+f"(c[1]), "+f"(c[2]), "+f"(c[3])
        : "r"(a[0]), "r"(a[1]), "r"(a[2]), "r"(a[3]), "r"(b[0]), "r"(b[1]));
}

// W[K][N] -> planes [3][N][K] (transpose + split)
__global__ void split_wt_kernel(const float* __restrict__ W,
                                __nv_bfloat16* __restrict__ o, int K, int N) {
    int idx = blockIdx.x * blockDim.x + threadIdx.x;
    if (idx >= K * N) return;
    int k = idx / N, n = idx % N;
    __nv_bfloat16 h, m, l;
    split3(W[idx], h, m, l);
    size_t pl = (size_t)K * N;
    size_t off = (size_t)n * K + k;
    o[off] = h; o[pl + off] = m; o[2 * pl + off] = l;
}

// ---------------- HMMA split GEMM --------------------------------------------
// A: fp32 [M][K]. B: 3 bf16 planes [3][ldN][K] (=W^T). Out: fp32 relu [M][ldN].
// In-kernel A split to 3 bf16 planes; convert overlapped behind tensor work.
// Each thread converts exactly the chunks it cp.async'd (wait_group suffices).
#define TROW 80                            // 64B data + 16B pad
#define TILE_B (128 * TROW)                // 10240
#define APL_B (3 * TILE_B)                 // 30720
#define BPL_B (3 * TILE_B)                 // 30720
#define FST_B (128 * 144)                  // 18432 (fp32 tile, 36-float stride)
#define BUF_B (APL_B + BPL_B + FST_B)      // 79872
#define HSMEM2 (2 * BUF_B)                 // 159744

__global__ void __launch_bounds__(256, 1)
hmma_gemm(const float* __restrict__ Af, const __nv_bfloat16* __restrict__ Bp,
          const float* __restrict__ bias, float* __restrict__ Cout,
          int K, int ldN)
{
    extern __shared__ char smem[];
    __shared__ float sbias[128];
    const uint32_t sb = (uint32_t)__cvta_generic_to_shared(smem);
    const int tid = threadIdx.x, wid = tid >> 5, lane = tid & 31;
    const int brow = blockIdx.y * 128, bcol = blockIdx.x * 128;
    const int mbase = (wid >> 2) * 64;       // warp 64x32 tile
    const int nbase = (wid & 3) * 32;
    const size_t bplane = (size_t)ldN * K;

    if (tid < 128) sbias[tid] = bias[bcol + tid];

    const char* Bg = (const char*)Bp;
    const int crow = tid >> 2;              // B tile chunk row (0..63)
    const int ccol = (tid & 3) * 16;

    auto load_kt = [&](int kt, int buf) {
        char* st = smem + buf * BUF_B;
        // B planes (bf16, pre-split weights)
#pragma unroll
        for (int half = 0; half < 2; half++) {
            int row = crow + half * 64;
#pragma unroll
            for (int p = 0; p < 3; p++) {
                cp_async16(st + APL_B + p * TILE_B + row * TROW + ccol,
                    Bg + ((size_t)p * bplane + (size_t)(bcol + row) * K) * 2
                       + (size_t)kt * 64 + ccol);
            }
        }
        // fp32 A tile into stage; 1024 16B chunks, 4 per thread
        char* fs = st + APL_B + BPL_B;
#pragma unroll
        for (int i = 0; i < 4; i++) {
            int c = tid + i * 256;
            int row = c >> 3, col = c & 7;
            cp_async16(fs + row * 144 + col * 16,
                (const char*)(Af + (size_t)(brow + row) * K + kt * 32 + col * 4));
        }
    };

    // convert own chunks: fp32 stage(buf) -> 3 bf16 A planes(buf)
    auto convert_own = [&](int buf) {
        const float* fs = (const float*)(smem + buf * BUF_B + APL_B + BPL_B);
        char* ap = smem + buf * BUF_B;
#pragma unroll
        for (int i = 0; i < 4; i++) {
            int c = tid + i * 256;
            int row = c >> 3, col = c & 7;
            float4 v = *(const float4*)(fs + row * 36 + col * 4);
            float vv[4] = {v.x, v.y, v.z, v.w};
            __nv_bfloat16 h[4], mm[4], l[4];
#pragma unroll
            for (int e = 0; e < 4; e++) split3(vv[e], h[e], mm[e], l[e]);
            const uint32_t off = row * TROW + col * 8;
            *(__nv_bfloat162*)(ap + off)                  = __halves2bfloat162(h[0], h[1]);
            *(__nv_bfloat162*)(ap + off + 4)              = __halves2bfloat162(h[2], h[3]);
            *(__nv_bfloat162*)(ap + TILE_B + off)         = __halves2bfloat162(mm[0], mm[1]);
            *(__nv_bfloat162*)(ap + TILE_B + off + 4)     = __halves2bfloat162(mm[2], mm[3]);
            *(__nv_bfloat162*)(ap + 2 * TILE_B + off)     = __halves2bfloat162(l[0], l[1]);
            *(__nv_bfloat162*)(ap + 2 * TILE_B + off + 4) = __halves2bfloat162(l[2], l[3]);
        }
    };

    float acc[4][4][4];
#pragma unroll
    for (int i = 0; i < 4; i++)
#pragma unroll
        for (int j = 0; j < 4; j++)
#pragma unroll
            for (int q = 0; q < 4; q++) acc[i][j][q] = 0.f;

    const int NT = K / 32;
    load_kt(0, 0); CP_COMMIT();
    load_kt(1, 1); CP_COMMIT();
    asm volatile("cp.async.wait_group 1;");   // own tile-0 chunks landed
    convert_own(0);

    const int a_r  = (lane & 15);
    const int a_kc = (lane & 16) ? 16 : 0;
    const int b_n  = (lane & 7) + ((lane & 16) ? 8 : 0);
    const int b_kc = (lane & 8) ? 16 : 0;

    const int pa[6] = {0, 0, 1, 1, 0, 2};
    const int pb[6] = {0, 1, 0, 1, 2, 0};

    for (int kt = 0; kt < NT; kt++) {
        const int buf = kt & 1;
        __syncthreads();   // B1: convert(kt) visible; prior loads into buf done

        const uint32_t stb = sb + buf * BUF_B;
#pragma unroll
        for (int k16 = 0; k16 < 2; k16++) {
            const int kk = k16 * 32;

            uint32_t afr[3][4][4];
#pragma unroll
            for (int p = 0; p < 3; p++) {
                uint32_t base = stb + p * TILE_B + kk + a_kc;
#pragma unroll
                for (int mf = 0; mf < 4; mf++) {
                    uint32_t ad = base + (mbase + mf * 16 + a_r) * TROW;
                    ldsm_x4(afr[p][mf][0], afr[p][mf][1], afr[p][mf][2], afr[p][mf][3], ad);
                }
            }
            uint32_t bfr[3][4][2];
#pragma unroll
            for (int p = 0; p < 3; p++) {
                uint32_t base = stb + APL_B + p * TILE_B + kk + b_kc;
#pragma unroll
                for (int nf2 = 0; nf2 < 2; nf2++) {
                    uint32_t bd = base + (nbase + nf2 * 16 + b_n) * TROW;
                    uint32_t r0, r1, r2, r3;
                    ldsm_x4(r0, r1, r2, r3, bd);
                    bfr[p][nf2 * 2 + 0][0] = r0; bfr[p][nf2 * 2 + 0][1] = r1;
                    bfr[p][nf2 * 2 + 1][0] = r2; bfr[p][nf2 * 2 + 1][1] = r3;
                }
            }
#pragma unroll
            for (int pr = 0; pr < 6; pr++) {
#pragma unroll
                for (int mf = 0; mf < 4; mf++)
#pragma unroll
                    for (int nf = 0; nf < 4; nf++)
                        hmma16816(acc[mf][nf], afr[pa[pr]][mf], bfr[pb[pr]][nf]);
            }
        }

        __syncthreads();   // B2: all warps done reading buf -> safe to refill
        if (kt + 2 < NT) { load_kt(kt + 2, buf); CP_COMMIT(); }
        if (kt + 1 < NT) {
            if (kt + 2 < NT) asm volatile("cp.async.wait_group 1;");
            else             asm volatile("cp.async.wait_group 0;");
            convert_own(buf ^ 1);     // overlaps with tensor-pipe drain of MMA(kt)
        }
    }

    // ---- epilogue: bias + relu -> fp32 ----
    const int qr = lane >> 2, qc = (lane & 3) * 2;
#pragma unroll
    for (int mf = 0; mf < 4; mf++) {
#pragma unroll
        for (int half = 0; half < 2; half++) {
            const int row = brow + mbase + mf * 16 + qr + half * 8;
#pragma unroll
            for (int nf = 0; nf < 4; nf++) {
                const int colL = nbase + nf * 8 + qc;
                float v0 = fmaxf(acc[mf][nf][half * 2 + 0] + sbias[colL],     0.f);
                float v1 = fmaxf(acc[mf][nf][half * 2 + 1] + sbias[colL + 1], 0.f);
                *(float2*)(Cout + (size_t)row * ldN + bcol + colL) = make_float2(v0, v1);
            }
        }
    }
}

// ---------------- SIMT FFMA2 GEMM (D-chain) ----------------------------------
__device__ __forceinline__ float act_apply(float v, int ACT) {
    if (ACT == 1) return v > 0.f ? v : 0.f;
    if (ACT == 2) return __fdividef(1.f, 1.f + __expf(-v));
    return v;
}

template<int BM, int BN, int BK, int ACT>
__global__ void __launch_bounds__((BM / 16) * (BN / 4), 2)
gemm2(const float* __restrict__ A, const float* __restrict__ W,
      const float* __restrict__ bias, float* __restrict__ Cmat,
      int K, int N)
{
    constexpr int TN = 4;
    constexpr int RX = BN / TN, RY = BM / 16, THREADS = RX * RY;
    constexpr int GROUPS = THREADS / BM;
    constexpr int KC  = BK / GROUPS;
    constexpr int AF4 = KC / 4;
    constexpr int WC  = (BK * BN) / (4 * THREADS);
    constexpr int BMP = BM + 4;
    constexpr int N4  = BN / 4;

    extern __shared__ float smemf[];
    float (*As)[BK][BMP] = (float (*)[BK][BMP])smemf;
    float (*Ws)[BK][BN]  = (float (*)[BK][BN])(smemf + 2 * BK * BMP);

    const int tid  = threadIdx.x;
    const int tcol = tid % RX;
    const int trow = tid / RX;
    const int brow = blockIdx.y * BM;
    const int bcol = blockIdx.x * BN;

    const int arow = tid % BM;
    const int akb  = (tid / BM) * KC;
    const float* Arow = A + (size_t)(brow + arow) * K + akb;

    ull acc2[8][TN];
#pragma unroll
    for (int i = 0; i < 8; i++)
#pragma unroll
        for (int j = 0; j < TN; j++) acc2[i][j] = 0ull;

    float4 areg[AF4];
    const int nt = K / BK;

#pragma unroll
    for (int q = 0; q < AF4; q++) areg[q] = *(const float4*)(Arow + q * 4);
#pragma unroll
    for (int i = 0; i < WC; i++) {
        int idx = tid + i * THREADS;
        int k = idx / N4, n4 = idx % N4;
        cp_async16(&Ws[0][k][n4 * 4], W + (size_t)k * N + bcol + n4 * 4);
    }
    CP_COMMIT();
#pragma unroll
    for (int q = 0; q < AF4; q++) {
        As[0][akb + q * 4 + 0][arow] = areg[q].x;
        As[0][akb + q * 4 + 1][arow] = areg[q].y;
        As[0][akb + q * 4 + 2][arow] = areg[q].z;
        As[0][akb + q * 4 + 3][arow] = areg[q].w;
    }
    asm volatile("cp.async.wait_group 0;");
    __syncthreads();

    for (int t = 0; t < nt; t++) {
        const int cb = t & 1;
        const bool more = (t + 1 < nt);
        if (more) {
            const float* Ap2 = Arow + (size_t)(t + 1) * BK;
#pragma unroll
            for (int q = 0; q < AF4; q++) areg[q] = *(const float4*)(Ap2 + q * 4);
            const float* Wp = W + (size_t)(t + 1) * BK * N + bcol;
#pragma unroll
            for (int i = 0; i < WC; i++) {
                int idx = tid + i * THREADS;
                int k = idx / N4, n4 = idx % N4;
                cp_async16(&Ws[cb ^ 1][k][n4 * 4], Wp + (size_t)k * N + n4 * 4);
            }
            CP_COMMIT();
        }
#pragma unroll
        for (int k = 0; k < BK; k++) {
            float4 wv = *(const float4*)&Ws[cb][k][tcol * 4];
            ull wb0, wb1, wb2, wb3;
            asm("mov.b64 %0, {%1, %1};" : "=l"(wb0) : "f"(wv.x));
            asm("mov.b64 %0, {%1, %1};" : "=l"(wb1) : "f"(wv.y));
            asm("mov.b64 %0, {%1, %1};" : "=l"(wb2) : "f"(wv.z));
            asm("mov.b64 %0, {%1, %1};" : "=l"(wb3) : "f"(wv.w));
            const float* ab = &As[cb][k][trow * 16];
            ulonglong2 p01 = *(const ulonglong2*)(ab + 0);
            ulonglong2 p23 = *(const ulonglong2*)(ab + 4);
            ulonglong2 p45 = *(const ulonglong2*)(ab + 8);
            ulonglong2 p67 = *(const ulonglong2*)(ab + 12);
            ull ap[8] = {p01.x, p01.y, p23.x, p23.y, p45.x, p45.y, p67.x, p67.y};
#pragma unroll
            for (int i = 0; i < 8; i++) {
                asm("fma.rn.f32x2 %0, %1, %2, %0;" : "+l"(acc2[i][0]) : "l"(ap[i]), "l"(wb0));
                asm("fma.rn.f32x2 %0, %1, %2, %0;" : "+l"(acc2[i][1]) : "l"(ap[i]), "l"(wb1));
                asm("fma.rn.f32x2 %0, %1, %2, %0;" : "+l"(acc2[i][2]) : "l"(ap[i]), "l"(wb2));
                asm("fma.rn.f32x2 %0, %1, %2, %0;" : "+l"(acc2[i][3]) : "l"(ap[i]), "l"(wb3));
            }
        }
        if (more) {
#pragma unroll
            for (int q = 0; q < AF4; q++) {
                As[cb ^ 1][akb + q * 4 + 0][arow] = areg[q].x;
                As[cb ^ 1][akb + q * 4 + 1][arow] = areg[q].y;
                As[cb ^ 1][akb + q * 4 + 2][arow] = areg[q].z;
                As[cb ^ 1][akb + q * 4 + 3][arow] = areg[q].w;
            }
            asm volatile("cp.async.wait_group 0;");
        }
        __syncthreads();
    }

    const int colb = bcol + tcol * 4;
    float4 bv = *(const float4*)(bias + colb);
#pragma unroll
    for (int i2 = 0; i2 < 8; i2++) {
        int row0 = brow + trow * 16 + 2 * i2;
        float e0, o0, e1, o1, e2, o2, e3, o3;
        asm("mov.b64 {%0, %1}, %2;" : "=f"(e0), "=f"(o0) : "l"(acc2[i2][0]));
        asm("mov.b64 {%0, %1}, %2;" : "=f"(e1), "=f"(o1) : "l"(acc2[i2][1]));
        asm("mov.b64 {%0, %1}, %2;" : "=f"(e2), "=f"(o2) : "l"(acc2[i2][2]));
        asm("mov.b64 {%0, %1}, %2;" : "=f"(e3), "=f"(o3) : "l"(acc2[i2][3]));
        float4 re, ro;
        re.x = act_apply(e0 + bv.x, ACT); re.y = act_apply(e1 + bv.y, ACT);
        re.z = act_apply(e2 + bv.z, ACT); re.w = act_apply(e3 + bv.w, ACT);
        ro.x = act_apply(o0 + bv.x, ACT); ro.y = act_apply(o1 + bv.y, ACT);
        ro.z = act_apply(o2 + bv.z, ACT); ro.w = act_apply(o3 + bv.w, ACT);
        *(float4*)(Cmat + (size_t)row0 * N + colb)       = re;
        *(float4*)(Cmat + (size_t)(row0 + 1) * N + colb) = ro;
    }
}

// d[r] = d2[r,:] . D3 + db3   (K = 64)
__global__ void dot_kernel(const float* __restrict__ d2, const float* __restrict__ D3,
                           const float* __restrict__ db3, float* __restrict__ dd)
{
    int gw   = (blockIdx.x * blockDim.x + threadIdx.x) >> 5;
    int lane = threadIdx.x & 31;
    if (gw >= MR) return;
    const float* row = d2 + (size_t)gw * 64;
    float s = row[lane] * D3[lane] + row[lane + 32] * D3[lane + 32];
#pragma unroll
    for (int o = 16; o > 0; o >>= 1) s += __shfl_down_sync(0xffffffffu, s, o);
    if (lane == 0) dd[gw] = s + db3[0];
}

// Per-bag: gumbel softmax, top-20 keep (stable), re-softmax, aggregate, project.
__global__ void __launch_bounds__(128)
final_kernel(const float* __restrict__ dd, const float* __restrict__ m,
             const float* __restrict__ u, const float* __restrict__ h3,
             const float* __restrict__ E, const float* __restrict__ eb,
             float* __restrict__ out_w, float* __restrict__ out_s)
{
    const int bag = blockIdx.x;
    const int t   = threadIdx.x;

    __shared__ float sm[64];
    __shared__ float wf[64];
    __shared__ float red[128];

    float z = 0.f;
    if (t < 64) {
        float logit = m[bag * 64 + t] * dd[bag * 64 + t];
        float uu = u[bag * 64 + t];
        float g = -logf(-logf(uu));
        z = (logit + g) / TAU_F;
    }

    red[t] = (t < 64) ? z : -INFINITY;
    __syncthreads();
#pragma unroll
    for (int s = 64; s >= 1; s >>= 1) {
        if (t < s) red[t] = fmaxf(red[t], red[t + s]);
        __syncthreads();
    }
    float zmax = red[0];
    __syncthreads();

    float e = (t < 64) ? expf(z - zmax) : 0.f;
    red[t] = e;
    __syncthreads();
#pragma unroll
    for (int s = 64; s >= 1; s >>= 1) {
        if (t < s) red[t] += red[t + s];
        __syncthreads();
    }
    float psum = red[0];
    __syncthreads();

    float p = e / psum;
    if (t < 64) sm[t] = p;
    __syncthreads();

    int keep = 0;
    if (t < 64) {
        int pos = 0;
#pragma unroll 8
        for (int j = 0; j < 64; j++) {
            float o = sm[j];
            pos += (o < p) || (o == p && j < t);
        }
        keep = (pos >= 44);
    }

    red[t] = (t < 64 && keep) ? p : -INFINITY;
    __syncthreads();
#pragma unroll
    for (int s = 64; s >= 1; s >>= 1) {
        if (t < s) red[t] = fmaxf(red[t], red[t + s]);
        __syncthreads();
    }
    float m2 = red[0];
    __syncthreads();

    float e2 = (t < 64 && keep) ? expf(p - m2) : 0.f;
    red[t] = e2;
    __syncthreads();
#pragma unroll
    for (int s = 64; s >= 1; s >>= 1) {
        if (t < s) red[t] += red[t + s];
        __syncthreads();
    }
    float s2 = red[0];
    __syncthreads();

    float wfin = (t < 64 && keep) ? (e2 / s2) : 0.f;
    if (t < 64) {
        wf[t] = wfin;
        out_w[bag * 64 + t] = wfin;
    }
    __syncthreads();

    const float* hb = h3 + (size_t)bag * 64 * 128;
    float agg = 0.f;
#pragma unroll 8
    for (int c = 0; c < 64; c++) agg += wf[c] * hb[c * 128 + t];
    red[t] = agg * E[t];
    __syncthreads();
#pragma unroll
    for (int s = 64; s >= 1; s >>= 1) {
        if (t < s) red[t] += red[t + s];
        __syncthreads();
    }
    if (t == 0) out_s[bag] = red[0] + eb[0];
}

// ---------------- launch ------------------------------------------------------
extern "C" void kernel_launch(void* const* d_in, const int* in_sizes, int n_in,
                              void* d_out, int out_size)
{
    const float* x   = (const float*)d_in[0];
    const float* m   = (const float*)d_in[1];
    const float* u   = (const float*)d_in[2];
    const float* W1  = (const float*)d_in[3];
    const float* b1  = (const float*)d_in[4];
    const float* W2  = (const float*)d_in[5];
    const float* b2  = (const float*)d_in[6];
    const float* W3  = (const float*)d_in[7];
    const float* b3  = (const float*)d_in[8];
    const float* D1  = (const float*)d_in[9];
    const float* db1 = (const float*)d_in[10];
    const float* D2  = (const float*)d_in[11];
    const float* db2 = (const float*)d_in[12];
    const float* D3  = (const float*)d_in[13];
    const float* db3 = (const float*)d_in[14];
    const float* E   = (const float*)d_in[15];
    const float* eb  = (const float*)d_in[16];
    float* out = (float*)d_out;

    __nv_bfloat16 *w1t, *w2t, *w3t;
    float *h1f, *h2f, *h3, *d1, *d2, *dd;
    cudaGetSymbolAddress((void**)&w1t, g_w1t);
    cudaGetSymbolAddress((void**)&w2t, g_w2t);
    cudaGetSymbolAddress((void**)&w3t, g_w3t);
    cudaGetSymbolAddress((void**)&h1f, g_h1f);
    cudaGetSymbolAddress((void**)&h2f, g_h2f);
    cudaGetSymbolAddress((void**)&h3,  g_h3);
    cudaGetSymbolAddress((void**)&d1,  g_d1);
    cudaGetSymbolAddress((void**)&d2,  g_d2);
    cudaGetSymbolAddress((void**)&dd,  g_dd);

    constexpr int S128 = (2 * 32 * 132 + 2 * 32 * 128) * 4;
    constexpr int S64  = (2 * 16 * 132 + 2 * 16 * 64) * 4;

    static int attr_done = 0;
    if (!attr_done) {
        cudaFuncSetAttribute(hmma_gemm, cudaFuncAttributeMaxDynamicSharedMemorySize, HSMEM2);
        cudaFuncSetAttribute(gemm2<128,128,32,2>, cudaFuncAttributeMaxDynamicSharedMemorySize, S128);
        cudaFuncSetAttribute(gemm2<128, 64,16,2>, cudaFuncAttributeMaxDynamicSharedMemorySize, S64);
        attr_done = 1;
    }

    // weight splits (tiny)
    split_wt_kernel<<<(512 * 256 + 255) / 256, 256>>>(W1, w1t, 512, 256);
    split_wt_kernel<<<(256 * 256 + 255) / 256, 256>>>(W2, w2t, 256, 256);
    split_wt_kernel<<<(256 * 128 + 255) / 256, 256>>>(W3, w3t, 256, 128);

    // h-chain on HMMA (exact-fp32 via 3-split/6-product), fp32 in/out
    hmma_gemm<<<dim3(2, MR / 128), 256, HSMEM2>>>(x,   w1t, b1, h1f, 512, 256);
    hmma_gemm<<<dim3(2, MR / 128), 256, HSMEM2>>>(h1f, w2t, b2, h2f, 256, 256);
    hmma_gemm<<<dim3(1, MR / 128), 256, HSMEM2>>>(h2f, w3t, b3, h3,  256, 128);

    // D-chain (SIMT FFMA2)
    gemm2<128,128,32,2><<<dim3(1, MR / 128), 256, S128>>>(h3, D1, db1, d1, 128, 128);
    gemm2<128, 64,16,2><<<dim3(1, MR / 128), 128, S64>>>(d1, D2, db2, d2, 128, 64);
    dot_kernel<<<MR / 8, 256>>>(d2, D3, db3, dd);
    final_kernel<<<NB, 128>>>(dd, m, u, h3, E, eb, out, out + MR);
}